// round 7
// baseline (speedup 1.0000x reference)
#include <cuda_runtime.h>
#include <math.h>

#define FRAME_SIZE 160
#define LPC_N 16
#define T_LEN 2400
#define T4 (T_LEN / 4)              // 600 float4 per row
#define N_FRAMES 15
#define B_SZ 1024

#define ROWP (T_LEN + LPC_N)        // 2416 floats per scratch row (16 = zero pad)
#define ROWP4 (ROWP / 4)            // 604 float4

#define SPT 8                       // samples per thread in pass 2
#define P2_WORK (B_SZ * T_LEN / SPT)        // 307200 threads
#define P1_DEC  (B_SZ * T4)                 // 614400 float4 decodes
#define P1_PAD  (B_SZ * (LPC_N / 4))        // 4096 pad float4 writes
#define P1_WORK (P1_DEC + P1_PAD)

#define SCALE    (255.0f / 32768.0f)
#define SCALE_1  (32768.0f / 255.0f)

// linear-domain signal with 16-sample zero history per row
__device__ float g_lin[(size_t)B_SZ * ROWP];

__device__ __forceinline__ float ex2_approx(float x) {
    float y; asm("ex2.approx.f32 %0, %1;" : "=f"(y) : "f"(x)); return y;
}
__device__ __forceinline__ float lg2_approx(float x) {
    float y; asm("lg2.approx.f32 %0, %1;" : "=f"(y) : "f"(x)); return y;
}

// mu-law (0..255) -> linear.  exp(u/128*ln256) == 2^(u/16)
__device__ __forceinline__ float u2l(float v) {
    float u = v - 128.0f;
    float m = fmaf(SCALE_1, ex2_approx(fabsf(u) * 0.0625f), -SCALE_1);
    return copysignf(m, u);
}
// l2u(-a) = clip(128 - copysign(16*log2(1 + SCALE*|a|), a), 0, 255)
__device__ __forceinline__ float l2u_neg(float a) {
    float u = lg2_approx(fmaf(SCALE, fabsf(a), 1.0f));
    float s = copysignf(16.0f, a);
    return fminf(fmaxf(fmaf(-s, u, 128.0f), 0.0f), 255.0f);
}

// ---------------- Pass 1: mu-law decode, pad-aware layout ----------------
__global__ __launch_bounds__(256)
void decode_kernel(const float4* __restrict__ sig) {
    int idx = blockIdx.x * 256 + threadIdx.x;
    float4* lin4 = (float4*)g_lin;
    if (idx < P1_DEC) {
        int b = idx / T4;
        int i = idx - b * T4;
        float4 v = sig[idx];
        float4 d;
        d.x = u2l(v.x); d.y = u2l(v.y); d.z = u2l(v.z); d.w = u2l(v.w);
        lin4[b * ROWP4 + 4 + i] = d;
    } else if (idx < P1_WORK) {
        int k = idx - P1_DEC;
        int b = k >> 2;
        int q = k & 3;
        lin4[b * ROWP4 + q] = make_float4(0.f, 0.f, 0.f, 0.f);
    }
}

// ---------------- Pass 2: 16-tap FIR + mu-law encode ----------------
// Thread s: row b = s/300, slot j = s%300, produces samples [8j .. 8j+7].
// Window = g_lin[b][8j .. 8j+23]  (history pad makes all indices valid).
__global__ __launch_bounds__(256)
void fir_kernel(const float* __restrict__ lpc,
                float4* __restrict__ out) {
    int s = blockIdx.x * 256 + threadIdx.x;
    if (s >= P2_WORK) return;
    int b = s / (T_LEN / SPT);          // / 300
    int j = s - b * (T_LEN / SPT);

    const float4* row = (const float4*)(g_lin + (size_t)b * ROWP);

    // 6 independent window loads (24 samples) — L2/L1-hot linear data
    float4 w0 = row[2 * j];
    float4 w1 = row[2 * j + 1];
    float4 w2 = row[2 * j + 2];
    float4 w3 = row[2 * j + 3];
    float4 w4 = row[2 * j + 4];
    float4 w5 = row[2 * j + 5];

    // 16 per-frame coefficients: frame f = (8j)/160 = j/20
    int f = j / (FRAME_SIZE / SPT);
    const float4* lrow = (const float4*)(lpc) + b * (N_FRAMES * LPC_N / 4) + f * (LPC_N / 4);
    float4 c0 = lrow[0], c1 = lrow[1], c2 = lrow[2], c3 = lrow[3];

    float x[24] = { w0.x, w0.y, w0.z, w0.w, w1.x, w1.y, w1.z, w1.w,
                    w2.x, w2.y, w2.z, w2.w, w3.x, w3.y, w3.z, w3.w,
                    w4.x, w4.y, w4.z, w4.w, w5.x, w5.y, w5.z, w5.w };
    float c[LPC_N] = { c0.x, c0.y, c0.z, c0.w, c1.x, c1.y, c1.z, c1.w,
                       c2.x, c2.y, c2.z, c2.w, c3.x, c3.y, c3.z, c3.w };

    // a[jj] = sum_i c[i] * x[16 + jj - i]
    float a[SPT];
#pragma unroll
    for (int jj = 0; jj < SPT; ++jj) a[jj] = 0.0f;
#pragma unroll
    for (int i = 0; i < LPC_N; ++i) {
#pragma unroll
        for (int jj = 0; jj < SPT; ++jj)
            a[jj] = fmaf(c[i], x[16 + jj - i], a[jj]);
    }

    float4 r0, r1;
    r0.x = l2u_neg(a[0]); r0.y = l2u_neg(a[1]); r0.z = l2u_neg(a[2]); r0.w = l2u_neg(a[3]);
    r1.x = l2u_neg(a[4]); r1.y = l2u_neg(a[5]); r1.z = l2u_neg(a[6]); r1.w = l2u_neg(a[7]);

    out[2 * s]     = r0;   // b*600 + 2j == 2s
    out[2 * s + 1] = r1;
}

extern "C" void kernel_launch(void* const* d_in, const int* in_sizes, int n_in,
                              void* d_out, int out_size) {
    const float4* sig = (const float4*)d_in[0];  // (B, 2400, 1) f32
    const float*  lpc = (const float*)d_in[1];   // (B, 15, 16) f32
    float4* out = (float4*)d_out;                // (B, 2400, 1) f32

    decode_kernel<<<(P1_WORK + 255) / 256, 256>>>(sig);
    fir_kernel<<<(P2_WORK + 255) / 256, 256>>>(lpc, out);
}

// round 8
// speedup vs baseline: 1.2143x; 1.2143x over previous
#include <cuda_runtime.h>
#include <math.h>

#define FRAME_SIZE 160
#define LPC_N 16
#define T_LEN 2400
#define T4 (T_LEN / 4)                 // 600 float4 per row
#define N_FRAMES 15
#define B_SZ 1024

#define FPB 3                          // frames per block
#define CHUNK (FRAME_SIZE * FPB)       // 480 samples
#define CHUNK4 (CHUNK / 4)             // 120 float4
#define CHUNKS_PER_B (N_FRAMES / FPB)  // 5
#define NTHREADS 128
#define NWORK CHUNK4                   // 120 work threads, 4 samples each

#define SCALE    (255.0f / 32768.0f)
#define SCALE_1  (32768.0f / 255.0f)

__device__ __forceinline__ float ex2_approx(float x) {
    float y; asm("ex2.approx.f32 %0, %1;" : "=f"(y) : "f"(x)); return y;
}
__device__ __forceinline__ float lg2_approx(float x) {
    float y; asm("lg2.approx.f32 %0, %1;" : "=f"(y) : "f"(x)); return y;
}

// mu-law (0..255) -> linear.  exp(u/128*ln256) == 2^(u/16)
// |u|*0.0625 : operand-abs folds into the FMUL for free in SASS.
__device__ __forceinline__ float u2l(float v) {
    float u = v - 128.0f;
    float m = fmaf(SCALE_1, ex2_approx(fabsf(u) * 0.0625f), -SCALE_1);
    return copysignf(m, u);
}
// l2u(-a) = clip(128 - copysign(16*log2(1 + SCALE*|a|), a), 0, 255)
__device__ __forceinline__ float l2u_neg(float a) {
    float u = lg2_approx(fmaf(SCALE, fabsf(a), 1.0f));
    float s = copysignf(16.0f, a);
    return fminf(fmaxf(fmaf(-s, u, 128.0f), 0.0f), 255.0f);
}

__device__ __forceinline__ float4 dec4(float4 v) {
    float4 d;
    d.x = u2l(v.x); d.y = u2l(v.y); d.z = u2l(v.z); d.w = u2l(v.w);
    return d;
}

// R2 champion structure + coefficient LDG prefetch (no coeff smem).
// One block per (row, 3-frame chunk); threads 0..119 produce 4 samples each.
__global__ __launch_bounds__(NTHREADS)
void diff_pred_kernel(const float4* __restrict__ sig,
                      const float*  __restrict__ lpc,
                      float4* __restrict__ out) {
    __shared__ __align__(16) float sx[LPC_N + CHUNK];   // halo + decoded chunk
    float4* sx4 = (float4*)sx;

    const int bx  = blockIdx.x;
    const int b   = bx / CHUNKS_PER_B;
    const int ck  = bx % CHUNKS_PER_B;
    const int tid = threadIdx.x;
    const int row4 = b * T4 + ck * CHUNK4;   // float4 index of chunk start

    // ---- front-batch ALL global loads (sig + this thread's coefficients) ----
    float4 c0, c1, c2, c3;
    if (tid < NWORK) {
        float4 v = sig[row4 + tid];
        // frame of this thread's 4 samples: tid/40 (0..2)
        const int f = tid / (FRAME_SIZE / 4);
        const float4* lrow = (const float4*)(lpc + (size_t)b * (N_FRAMES * LPC_N)
                                             + (ck * FPB + f) * LPC_N);
        c0 = lrow[0]; c1 = lrow[1]; c2 = lrow[2]; c3 = lrow[3];
        sx4[4 + tid] = dec4(v);
    } else if (tid < NWORK + 4) {
        // halo: 16 samples preceding the chunk (zeros in linear domain at t<0)
        int k = tid - NWORK;                 // 0..3
        sx4[k] = (ck == 0) ? make_float4(0.f, 0.f, 0.f, 0.f)
                           : dec4(sig[row4 - 4 + k]);
    }
    __syncthreads();

    if (tid >= NWORK) return;

    // 20-sample window sx[4*tid .. 4*tid+19] (5 LDS.128, front-batched)
    float x[20];
#pragma unroll
    for (int k = 0; k < 5; ++k) {
        float4 xx = sx4[tid + k];
        x[4 * k] = xx.x; x[4 * k + 1] = xx.y; x[4 * k + 2] = xx.z; x[4 * k + 3] = xx.w;
    }

    const float c[LPC_N] = { c0.x, c0.y, c0.z, c0.w, c1.x, c1.y, c1.z, c1.w,
                             c2.x, c2.y, c2.z, c2.w, c3.x, c3.y, c3.z, c3.w };

    // output sample 4*tid + j uses x[16 + j - i], i = 0..15
    float a0 = 0.f, a1 = 0.f, a2 = 0.f, a3 = 0.f;
#pragma unroll
    for (int i = 0; i < LPC_N; ++i) {
        a0 = fmaf(c[i], x[16 - i], a0);
        a1 = fmaf(c[i], x[17 - i], a1);
        a2 = fmaf(c[i], x[18 - i], a2);
        a3 = fmaf(c[i], x[19 - i], a3);
    }

    float4 r;
    r.x = l2u_neg(a0); r.y = l2u_neg(a1); r.z = l2u_neg(a2); r.w = l2u_neg(a3);
    out[row4 + tid] = r;
}

extern "C" void kernel_launch(void* const* d_in, const int* in_sizes, int n_in,
                              void* d_out, int out_size) {
    const float4* sig = (const float4*)d_in[0];  // (B, 2400, 1) f32
    const float*  lpc = (const float*)d_in[1];   // (B, 15, 16) f32
    float4* out = (float4*)d_out;                // (B, 2400, 1) f32

    dim3 grid(B_SZ * CHUNKS_PER_B);              // 5120 blocks
    dim3 block(NTHREADS);
    diff_pred_kernel<<<grid, block>>>(sig, lpc, out);
}